// round 15
// baseline (speedup 1.0000x reference)
#include <cuda_runtime.h>
#include <math.h>

#define BATCH 8
#define CIN 256
#define HH 100
#define WW 152
#define HW 15200
#define NC 81
#define NKEEP 100
#define NOUT1 (BATCH*CIN*NKEEP)   /* 204800 */

#define NTILES 7600       /* 8 * 25 * 38 */
#define TPB    950        /* tiles per batch image */
#define TPAD   7680       /* padded tile count (60 * 128) */

typedef unsigned long long ull;

// ---------------------------------------------------------------------------
// Device scratch (allocation-free per harness rules)
// ---------------------------------------------------------------------------
__device__ int   g_cls[BATCH*HW];
__device__ float g_pv[BATCH*HW];
__device__ ull   g_keys[BATCH*HW];
__device__ int   g_topk[BATCH*NKEEP];
// Winograd buffers
__device__ float g_U[(size_t)36*CIN*CIN];         // weight transform [k][ci][co]
__device__ float g_V[(size_t)36*CIN*TPAD];        // input transform  [k][ci][t]
__device__ float g_M[(size_t)36*CIN*TPAD];        // GEMM output      [k][co][t]

// Packed f32x2 helpers (SASS FFMA2 — exact IEEE fp32)
#define FMA2(d,a,b,c) asm("fma.rn.f32x2 %0, %1, %2, %3;" : "=l"(d) : "l"(a), "l"(b), "l"(c))
#define PACK2(d,lo,hi) asm("mov.b64 %0, {%1, %2};" : "=l"(d) : "f"(lo), "f"(hi))
#define UNPACK2(lo,hi,s) asm("mov.b64 {%0, %1}, %2;" : "=f"(lo), "=f"(hi) : "l"(s))

// ---------------------------------------------------------------------------
// Winograd F(4x4,3x3) weight transform: U = G g G^T, stored [k=36][ci][co]
// ---------------------------------------------------------------------------
__global__ void k_wino_w(const float* __restrict__ w1){
  int i = blockIdx.x*256 + threadIdx.x;
  if (i >= CIN*CIN) return;
  int co = i & 255, ci = i >> 8;
  float g[3][3];
  #pragma unroll
  for (int m=0;m<3;m++)
    #pragma unroll
    for (int j=0;j<3;j++)
      g[m][j] = w1[((size_t)(co*CIN+ci)*3+m)*3+j];
  float T1[6][3];
  #pragma unroll
  for (int j=0;j<3;j++){
    float g0=g[0][j], g1=g[1][j], g2=g[2][j];
    T1[0][j] = 0.25f*g0;
    T1[1][j] = (-g0-g1-g2)*(1.f/6.f);
    T1[2][j] = (-g0+g1-g2)*(1.f/6.f);
    T1[3][j] = g0*(1.f/24.f)+g1*(1.f/12.f)+g2*(1.f/6.f);
    T1[4][j] = g0*(1.f/24.f)-g1*(1.f/12.f)+g2*(1.f/6.f);
    T1[5][j] = g2;
  }
  #pragma unroll
  for (int r=0;r<6;r++){
    float t0=T1[r][0], t1=T1[r][1], t2=T1[r][2];
    float u[6];
    u[0] = 0.25f*t0;
    u[1] = (-t0-t1-t2)*(1.f/6.f);
    u[2] = (-t0+t1-t2)*(1.f/6.f);
    u[3] = t0*(1.f/24.f)+t1*(1.f/12.f)+t2*(1.f/6.f);
    u[4] = t0*(1.f/24.f)-t1*(1.f/12.f)+t2*(1.f/6.f);
    u[5] = t2;
    #pragma unroll
    for (int c=0;c<6;c++)
      g_U[((size_t)(r*6+c)*CIN + ci)*CIN + co] = u[c];
  }
}

// ---------------------------------------------------------------------------
// Input transform: V = B^T d B per (tile, ci). Stored [k][ci][t].
// ---------------------------------------------------------------------------
__global__ void k_wino_in(const float* __restrict__ x){
  int t = blockIdx.x*256 + threadIdx.x;
  int ci = blockIdx.y;
  if (t >= NTILES) return;
  int b = t / TPB, rr = t - b*TPB;
  int ty = rr / 38, tx = rr - ty*38;
  int y0 = ty*4 - 1, xg0 = tx*4 - 1;
  const float* xp = x + ((size_t)b*CIN + ci)*HW;
  float d[6][6];
  #pragma unroll
  for (int m=0;m<6;m++){
    int gy = y0 + m;
    bool ry = ((unsigned)gy < HH);
    #pragma unroll
    for (int j=0;j<6;j++){
      int gx = xg0 + j;
      d[m][j] = (ry && (unsigned)gx < WW) ? xp[gy*WW + gx] : 0.f;
    }
  }
  float tmp[6][6];
  #pragma unroll
  for (int j=0;j<6;j++){
    float d0=d[0][j],d1=d[1][j],d2=d[2][j],d3=d[3][j],d4=d[4][j],d5=d[5][j];
    tmp[0][j] = 4.f*d0 - 5.f*d2 + d4;
    tmp[1][j] = -4.f*d1 - 4.f*d2 + d3 + d4;
    tmp[2][j] =  4.f*d1 - 4.f*d2 - d3 + d4;
    tmp[3][j] = -2.f*d1 - d2 + 2.f*d3 + d4;
    tmp[4][j] =  2.f*d1 - d2 - 2.f*d3 + d4;
    tmp[5][j] =  4.f*d1 - 5.f*d3 + d5;
  }
  #pragma unroll
  for (int i=0;i<6;i++){
    float r0=tmp[i][0],r1=tmp[i][1],r2=tmp[i][2],r3=tmp[i][3],r4=tmp[i][4],r5=tmp[i][5];
    float v[6];
    v[0] = 4.f*r0 - 5.f*r2 + r4;
    v[1] = -4.f*r1 - 4.f*r2 + r3 + r4;
    v[2] =  4.f*r1 - 4.f*r2 - r3 + r4;
    v[3] = -2.f*r1 - r2 + 2.f*r3 + r4;
    v[4] =  2.f*r1 - r2 - 2.f*r3 + r4;
    v[5] =  4.f*r1 - 5.f*r3 + r5;
    #pragma unroll
    for (int c=0;c<6;c++)
      g_V[((size_t)(i*6+c)*CIN + ci)*TPAD + t] = v[c];
  }
}

// ---------------------------------------------------------------------------
// GEMM v3 (unchanged from R10/R11 win): 128co x 128t, ci chunks of 16.
// ---------------------------------------------------------------------------
__global__ __launch_bounds__(256,2) void k_gemm(){
  __shared__ __align__(16) ull s_v[2][16][128];   // (v,v) pairs, 32KB
  __shared__ __align__(16) ull s_w[2][16][64];    // (w0,w1) pairs, 16KB
  int tid = threadIdx.x;
  int t0  = blockIdx.x*128;
  int co0 = blockIdx.y*128;
  int kk  = blockIdx.z;
  int og = tid & 15;       // co group: 8 co (4 pairs)
  int tg = tid >> 4;       // t group: 8 t
  const float* Vk = g_V + (size_t)kk*CIN*TPAD;
  const float* Uk = g_U + (size_t)kk*CIN*CIN;

  ull acc[4][8];
  #pragma unroll
  for (int p=0;p<4;p++)
    #pragma unroll
    for (int j=0;j<8;j++) PACK2(acc[p][j], 0.f, 0.f);

  int sci  = tid >> 5;
  int scol = tid & 31;

  float4 rv0 = *(const float4*)&Vk[(size_t)sci*TPAD + t0 + scol*4];
  float4 rv1 = *(const float4*)&Vk[(size_t)(sci+8)*TPAD + t0 + scol*4];
  float4 rw0 = *(const float4*)&Uk[(size_t)sci*CIN + co0 + scol*4];
  float4 rw1 = *(const float4*)&Uk[(size_t)(sci+8)*CIN + co0 + scol*4];
  {
    ull d0,d1,d2,d3;
    PACK2(d0,rv0.x,rv0.x); PACK2(d1,rv0.y,rv0.y);
    PACK2(d2,rv0.z,rv0.z); PACK2(d3,rv0.w,rv0.w);
    ull* dst = &s_v[0][sci][scol*4];
    dst[0]=d0; dst[1]=d1; dst[2]=d2; dst[3]=d3;
    PACK2(d0,rv1.x,rv1.x); PACK2(d1,rv1.y,rv1.y);
    PACK2(d2,rv1.z,rv1.z); PACK2(d3,rv1.w,rv1.w);
    dst = &s_v[0][sci+8][scol*4];
    dst[0]=d0; dst[1]=d1; dst[2]=d2; dst[3]=d3;
    ull w0,w1;
    PACK2(w0,rw0.x,rw0.y); PACK2(w1,rw0.z,rw0.w);
    s_w[0][sci][scol*2]   = w0;
    s_w[0][sci][scol*2+1] = w1;
    PACK2(w0,rw1.x,rw1.y); PACK2(w1,rw1.z,rw1.w);
    s_w[0][sci+8][scol*2]   = w0;
    s_w[0][sci+8][scol*2+1] = w1;
  }
  __syncthreads();

  #pragma unroll 1
  for (int c=0; c<16; c++){
    int buf = c & 1;
    if (c+1 < 16){
      int cin = (c+1)*16;
      rv0 = *(const float4*)&Vk[(size_t)(cin+sci)*TPAD + t0 + scol*4];
      rv1 = *(const float4*)&Vk[(size_t)(cin+sci+8)*TPAD + t0 + scol*4];
      rw0 = *(const float4*)&Uk[(size_t)(cin+sci)*CIN + co0 + scol*4];
      rw1 = *(const float4*)&Uk[(size_t)(cin+sci+8)*CIN + co0 + scol*4];
    }

    #pragma unroll 8
    for (int ci=0; ci<16; ci++){
      ulonglong2 v01 = *(const ulonglong2*)&s_v[buf][ci][tg*8];
      ulonglong2 v23 = *(const ulonglong2*)&s_v[buf][ci][tg*8+2];
      ulonglong2 v45 = *(const ulonglong2*)&s_v[buf][ci][tg*8+4];
      ulonglong2 v67 = *(const ulonglong2*)&s_v[buf][ci][tg*8+6];
      ulonglong2 wa = *(const ulonglong2*)&s_w[buf][ci][og*4];
      ulonglong2 wb = *(const ulonglong2*)&s_w[buf][ci][og*4+2];
      ull v[8] = {v01.x, v01.y, v23.x, v23.y, v45.x, v45.y, v67.x, v67.y};
      #pragma unroll
      for (int j=0;j<8;j++){
        FMA2(acc[0][j], v[j], wa.x, acc[0][j]);
        FMA2(acc[1][j], v[j], wa.y, acc[1][j]);
        FMA2(acc[2][j], v[j], wb.x, acc[2][j]);
        FMA2(acc[3][j], v[j], wb.y, acc[3][j]);
      }
    }

    if (c+1 < 16){
      int nb = buf ^ 1;
      ull d0,d1,d2,d3;
      PACK2(d0,rv0.x,rv0.x); PACK2(d1,rv0.y,rv0.y);
      PACK2(d2,rv0.z,rv0.z); PACK2(d3,rv0.w,rv0.w);
      ull* dst = &s_v[nb][sci][scol*4];
      dst[0]=d0; dst[1]=d1; dst[2]=d2; dst[3]=d3;
      PACK2(d0,rv1.x,rv1.x); PACK2(d1,rv1.y,rv1.y);
      PACK2(d2,rv1.z,rv1.z); PACK2(d3,rv1.w,rv1.w);
      dst = &s_v[nb][sci+8][scol*4];
      dst[0]=d0; dst[1]=d1; dst[2]=d2; dst[3]=d3;
      ull w0,w1;
      PACK2(w0,rw0.x,rw0.y); PACK2(w1,rw0.z,rw0.w);
      s_w[nb][sci][scol*2]   = w0;
      s_w[nb][sci][scol*2+1] = w1;
      PACK2(w0,rw1.x,rw1.y); PACK2(w1,rw1.z,rw1.w);
      s_w[nb][sci+8][scol*2]   = w0;
      s_w[nb][sci+8][scol*2+1] = w1;
    }
    __syncthreads();
  }

  float* Mk = g_M + (size_t)kk*CIN*TPAD;
  #pragma unroll
  for (int p=0;p<4;p++){
    float lo[8], hi[8];
    #pragma unroll
    for (int j=0;j<8;j++) UNPACK2(lo[j], hi[j], acc[p][j]);
    int co = co0 + og*8 + 2*p;
    float* r0 = &Mk[(size_t)co*TPAD + t0 + tg*8];
    float* r1 = &Mk[(size_t)(co+1)*TPAD + t0 + tg*8];
    *(float4*)r0     = make_float4(lo[0],lo[1],lo[2],lo[3]);
    *(float4*)(r0+4) = make_float4(lo[4],lo[5],lo[6],lo[7]);
    *(float4*)r1     = make_float4(hi[0],hi[1],hi[2],hi[3]);
    *(float4*)(r1+4) = make_float4(hi[4],hi[5],hi[6],hi[7]);
  }
}

// ---------------------------------------------------------------------------
// FUSED v4: output transform + bias/relu + 1x1 conv + softmax.
// Same structure as v3 (32 tiles, 512 threads, 2 px + co-half per thread)
// but the conv loop and epilogue are BRANCH-SPECIALIZED per half with
// compile-time pair counts -> zero per-FMA predication / runtime indexing.
// ---------------------------------------------------------------------------
#define NJ0 21   /* half 0: pairs j=0..20  -> co 0..41  */
#define NJ1 20   /* half 1: pairs j=21..40 -> co 42..81 (81 = pad) */

template<int J0, int NJ>
__device__ __forceinline__ void conv_accum(const float (*s_hid)[512],
                                           const ull (*s_w2)[41],
                                           int pxl, ull* accA, ull* accB){
  #pragma unroll 2
  for (int ci=0; ci<16; ci++){
    float vA = s_hid[ci][pxl];
    float vB = s_hid[ci][pxl+256];
    ull vdA, vdB; PACK2(vdA, vA, vA); PACK2(vdB, vB, vB);
    const ull* wp = s_w2[ci] + J0;
    #pragma unroll
    for (int j=0;j<NJ;j++){
      ull w = wp[j];
      FMA2(accA[j], vdA, w, accA[j]);
      FMA2(accB[j], vdB, w, accB[j]);
    }
  }
}

template<int J0, int NJ>
__device__ __forceinline__ void epi_maxwrite(const ull* acc, float* ob, int px,
                                             bool valid, float& M, float& best,
                                             int& bi){
  M = -1e30f; best = -1e30f; bi = 0;
  #pragma unroll
  for (int j=0;j<NJ;j++){
    int jj = J0 + j;
    float a, c; UNPACK2(a, c, acc[j]);
    if (valid) ob[(size_t)(2*jj)*HW + px] = a;
    if (2*jj < 80 && a > best){ best = a; bi = 2*jj; }
    M = fmaxf(M, a);
    if (2*jj+1 < 81){
      if (valid) ob[(size_t)(2*jj+1)*HW + px] = c;
      if (2*jj+1 < 80 && c > best){ best = c; bi = 2*jj+1; }
      M = fmaxf(M, c);
    }
  }
}

template<int J0, int NJ>
__device__ __forceinline__ float epi_expsum(const ull* acc, float Mg){
  float s = 0.f;
  #pragma unroll
  for (int j=0;j<NJ;j++){
    int jj = J0 + j;
    float a, c; UNPACK2(a, c, acc[j]);
    s += expf(a - Mg);
    if (2*jj+1 < 81) s += expf(c - Mg);
  }
  return s;
}

__global__ __launch_bounds__(512,1) void k_fused_out(const float* __restrict__ b1,
                                                     const float* __restrict__ w2,
                                                     const float* __restrict__ b2,
                                                     float* __restrict__ logits){
  __shared__ float s_hid[16][512];   // 32KB (reused in epilogue)
  __shared__ ull   s_w2[16][41];     // 5.25KB
  int tid = threadIdx.x;
  int t0 = blockIdx.x*32;
  int co16 = tid >> 5;
  int tl   = tid & 31;
  int t    = t0 + tl;
  int pxl  = tid & 255;
  int half = tid >> 8;

  ull accA[NJ0], accB[NJ0];
  if (half==0){
    #pragma unroll
    for (int j=0;j<NJ0;j++){
      float ba = b2[2*j];
      float bb = b2[2*j+1];
      PACK2(accA[j], ba, bb); accB[j] = accA[j];
    }
  } else {
    #pragma unroll
    for (int j=0;j<NJ1;j++){
      int jj = NJ0 + j;
      float ba = b2[2*jj];
      float bb = (2*jj+1 < 81) ? b2[2*jj+1] : 0.f;
      PACK2(accA[j], ba, bb); accB[j] = accA[j];
    }
    PACK2(accA[NJ0-1], 0.f, 0.f); accB[NJ0-1] = accA[NJ0-1];
  }

  #pragma unroll 1
  for (int ch=0; ch<16; ch++){
    __syncthreads();
    #pragma unroll 1
    for (int i=tid; i<16*41; i+=512){
      int j = i % 41; int ci = i/41;
      int cia = ch*16 + ci;
      float wa = w2[(2*j)*CIN + cia];
      float wb = (2*j+1 < 81) ? w2[(2*j+1)*CIN + cia] : 0.f;
      ull d; PACK2(d, wa, wb);
      s_w2[ci][j] = d;
    }
    {
      int co = ch*16 + co16;
      const float* Mp = g_M + (size_t)co*TPAD + t;
      float bv = b1[co];
      float tr0[6], tr1[6], tr2[6], tr3[6];
      #pragma unroll
      for (int j=0;j<6;j++){
        float m0 = Mp[(size_t)(0*6+j)*CIN*TPAD];
        float m1 = Mp[(size_t)(1*6+j)*CIN*TPAD];
        float m2 = Mp[(size_t)(2*6+j)*CIN*TPAD];
        float m3 = Mp[(size_t)(3*6+j)*CIN*TPAD];
        float m4 = Mp[(size_t)(4*6+j)*CIN*TPAD];
        float m5 = Mp[(size_t)(5*6+j)*CIN*TPAD];
        tr0[j] = m0+m1+m2+m3+m4;
        tr1[j] = m1-m2+2.f*m3-2.f*m4;
        tr2[j] = m1+m2+4.f*m3+4.f*m4;
        tr3[j] = m1-m2+8.f*m3-8.f*m4+m5;
      }
      float* hrow = &s_hid[co16][tl*16];
      #pragma unroll
      for (int r=0;r<4;r++){
        const float* tr = (r==0)?tr0:((r==1)?tr1:((r==2)?tr2:tr3));
        float r0=tr[0],r1=tr[1],r2=tr[2],r3=tr[3],r4=tr[4],r5=tr[5];
        float y0 = r0+r1+r2+r3+r4;
        float y1 = r1-r2+2.f*r3-2.f*r4;
        float y2 = r1+r2+4.f*r3+4.f*r4;
        float y3 = r1-r2+8.f*r3-8.f*r4+r5;
        hrow[r*4+0] = fmaxf(y0+bv, 0.f);
        hrow[r*4+1] = fmaxf(y1+bv, 0.f);
        hrow[r*4+2] = fmaxf(y2+bv, 0.f);
        hrow[r*4+3] = fmaxf(y3+bv, 0.f);
      }
    }
    __syncthreads();
    if (half==0) conv_accum<0,  NJ0>(s_hid, s_w2, pxl, accA, accB);
    else         conv_accum<NJ0,NJ1>(s_hid, s_w2, pxl, accA, accB);
  }

  // ---- epilogue ----
  __syncthreads();
  float* base = (float*)s_hid;
  float* redM = base;                 // [2][512]
  float* redB = base + 1024;
  float* redS = base + 2048;
  int*   redI = (int*)(base + 3072);

  #pragma unroll
  for (int s2=0;s2<2;s2++){
    int q = pxl + s2*256;
    int tile = t0 + (q >> 4);
    bool valid = (tile < NTILES);
    int b = tile / TPB, rr = tile - b*TPB;
    int ty = rr / 38, tx = rr - ty*38;
    int pos = q & 15;
    int px = (ty*4 + (pos>>2))*WW + tx*4 + (pos&3);
    float* ob = logits + (size_t)b*NC*HW;
    ull* acc = s2 ? accB : accA;
    float M, best; int bi;
    if (half==0) epi_maxwrite<0,  NJ0>(acc, ob, px, valid, M, best, bi);
    else         epi_maxwrite<NJ0,NJ1>(acc, ob, px, valid, M, best, bi);
    redM[half*512 + q] = M;
    redB[half*512 + q] = best;
    redI[half*512 + q] = bi;
  }
  __syncthreads();
  #pragma unroll
  for (int s2=0;s2<2;s2++){
    int q = pxl + s2*256;
    float Mg = fmaxf(redM[q], redM[512 + q]);
    ull* acc = s2 ? accB : accA;
    float s = (half==0) ? epi_expsum<0,NJ0>(acc, Mg)
                        : epi_expsum<NJ0,NJ1>(acc, Mg);
    redS[half*512 + q] = s;
  }
  __syncthreads();
  if (half==0){
    #pragma unroll
    for (int s2=0;s2<2;s2++){
      int q = pxl + s2*256;
      int tile = t0 + (q >> 4);
      if (tile >= NTILES) continue;
      int b = tile / TPB, rr = tile - b*TPB;
      int ty = rr / 38, tx = rr - ty*38;
      int pos = q & 15;
      int px = (ty*4 + (pos>>2))*WW + tx*4 + (pos&3);
      float Mg = fmaxf(redM[q], redM[512 + q]);
      float stot = redS[q] + redS[512 + q];
      float b0 = redB[q], b1v = redB[512 + q];
      int   i0 = redI[q], i1  = redI[512 + q];
      float bestg = b0; int big = i0;
      if (b1v > b0){ bestg = b1v; big = i1; }
      int gi = b*HW + px;
      g_pv[gi]  = expf(bestg - Mg) / stot;
      g_cls[gi] = big;
    }
  }
}

// ---------------------------------------------------------------------------
// score = p + 1 if local max (same-class strict neighbors) — unchanged.
// ---------------------------------------------------------------------------
__global__ void k_score(){
  int i = blockIdx.x*256 + threadIdx.x;
  if (i >= BATCH*HW) return;
  int b = i / HW, px = i - b*HW;
  int y = px / WW, xx = px - y*WW;
  float p = g_pv[i]; int cls = g_cls[i];
  bool flag = (p >= 1e-6f);
  if (flag){
    #pragma unroll
    for (int dy=-1; dy<=1; dy++){
      #pragma unroll
      for (int dx=-1; dx<=1; dx++){
        if (dy==0 && dx==0) continue;
        int ny = y+dy, nx = xx+dx;
        if ((unsigned)ny < HH && (unsigned)nx < WW){
          int j = b*HW + ny*WW + nx;
          if (g_cls[j]==cls && g_pv[j] > p) flag = false;
        }
      }
    }
  }
  float score = p + (flag ? 1.f : 0.f);
  g_keys[i] = (((ull)__float_as_uint(score))<<32)
              | (ull)(0xFFFFFFFFu - (unsigned)px);
}

// ---------------------------------------------------------------------------
// Top-100 v2 (unchanged from R11 win): stripe cache + shfl argmax.
// ---------------------------------------------------------------------------
__global__ void k_topk(){
  __shared__ ull s_val[256];
  __shared__ ull s_wv[8];
  __shared__ int s_wi[8];
  __shared__ int s_twin;
  int b = blockIdx.x, tid = threadIdx.x;
  int lane = tid & 31, wid = tid >> 5;
  ull* kb = g_keys + (size_t)b*HW;

  {
    ull m = 0ull;
    for (int i=tid; i<HW; i+=256){
      ull k = kb[i];
      if (k > m) m = k;
    }
    s_val[tid] = m;
  }
  __syncthreads();

  for (int it=0; it<NKEEP; it++){
    ull v = s_val[tid]; int idx = tid;
    #pragma unroll
    for (int off=16; off; off>>=1){
      ull ov  = __shfl_down_sync(0xFFFFFFFFu, v, off);
      int oi  = __shfl_down_sync(0xFFFFFFFFu, idx, off);
      if (ov > v){ v = ov; idx = oi; }
    }
    if (lane==0){ s_wv[wid] = v; s_wi[wid] = idx; }
    __syncthreads();
    if (tid==0){
      ull bv = s_wv[0]; int bidx = s_wi[0];
      #pragma unroll
      for (int w=1;w<8;w++)
        if (s_wv[w] > bv){ bv = s_wv[w]; bidx = s_wi[w]; }
      int wpx = (int)(0xFFFFFFFFu - (unsigned)(bv & 0xFFFFFFFFull));
      g_topk[b*NKEEP+it] = wpx;
      kb[wpx] = 0ull;
      s_twin = bidx;
    }
    __syncthreads();
    int twin = s_twin;
    if (wid==0){
      ull m = 0ull;
      int i0 = twin + lane*256, i1 = twin + (lane+32)*256;
      if (i0 < HW){ ull k = kb[i0]; if (k > m) m = k; }
      if (i1 < HW){ ull k = kb[i1]; if (k > m) m = k; }
      #pragma unroll
      for (int off=16; off; off>>=1){
        ull ov = __shfl_down_sync(0xFFFFFFFFu, m, off);
        if (ov > m) m = ov;
      }
      if (lane==0) s_val[twin] = m;
    }
    __syncthreads();
  }
}

// ---------------------------------------------------------------------------
// Gather x and pos at top-k indices. out layout: [proposals | pos | logits]
// ---------------------------------------------------------------------------
__global__ void k_gather(const float* __restrict__ x, const float* __restrict__ pos,
                         float* __restrict__ out){
  int i = blockIdx.x*256 + threadIdx.x;
  if (i >= NOUT1) return;
  int k = i % NKEEP; int t = i / NKEEP; int c = t % CIN; int b = t / CIN;
  int px = g_topk[b*NKEEP + k];
  out[i]         = x[((size_t)b*CIN + c)*HW + px];
  out[NOUT1 + i] = pos[(size_t)c*HW + px];
}

// ---------------------------------------------------------------------------
extern "C" void kernel_launch(void* const* d_in, const int* in_sizes, int n_in,
                              void* d_out, int out_size){
  (void)in_sizes; (void)n_in; (void)out_size;
  const float* x   = (const float*)d_in[0];
  const float* pos = (const float*)d_in[1];
  const float* w1  = (const float*)d_in[2];
  const float* b1  = (const float*)d_in[3];
  const float* w2  = (const float*)d_in[4];
  const float* b2  = (const float*)d_in[5];
  float* out = (float*)d_out;
  float* logits = out + 2*NOUT1;

  k_wino_w   <<<(CIN*CIN+255)/256, 256>>>(w1);
  k_wino_in  <<<dim3((NTILES+255)/256, CIN), 256>>>(x);
  k_gemm     <<<dim3(TPAD/128, CIN/128, 36), 256>>>();
  k_fused_out<<<TPAD/32, 512>>>(b1, w2, b2, logits);
  k_score    <<<(BATCH*HW+255)/256, 256>>>();
  k_topk     <<<BATCH, 256>>>();
  k_gather   <<<(NOUT1+255)/256, 256>>>(x, pos, out);
}

// round 16
// speedup vs baseline: 1.0671x; 1.0671x over previous
#include <cuda_runtime.h>
#include <math.h>

#define BATCH 8
#define CIN 256
#define HH 100
#define WW 152
#define HW 15200
#define NC 81
#define NKEEP 100
#define NOUT1 (BATCH*CIN*NKEEP)   /* 204800 */

#define NTILES 7600       /* 8 * 25 * 38 */
#define TPB    950        /* tiles per batch image */
#define TPAD   7680       /* padded tile count (60 * 128) */

typedef unsigned long long ull;

// ---------------------------------------------------------------------------
// Device scratch (allocation-free per harness rules)
// ---------------------------------------------------------------------------
__device__ int   g_cls[BATCH*HW];
__device__ float g_pv[BATCH*HW];
__device__ ull   g_keys[BATCH*HW];
__device__ int   g_topk[BATCH*NKEEP];
// Winograd buffers
__device__ float g_U[(size_t)36*CIN*CIN];         // weight transform [k][ci][co]
__device__ float g_V[(size_t)36*CIN*TPAD];        // input transform  [k][ci][t]
__device__ float g_M[(size_t)36*CIN*TPAD];        // GEMM output      [k][co][t]

// Packed f32x2 helpers (SASS FFMA2 — exact IEEE fp32)
#define FMA2(d,a,b,c) asm("fma.rn.f32x2 %0, %1, %2, %3;" : "=l"(d) : "l"(a), "l"(b), "l"(c))
#define PACK2(d,lo,hi) asm("mov.b64 %0, {%1, %2};" : "=l"(d) : "f"(lo), "f"(hi))
#define UNPACK2(lo,hi,s) asm("mov.b64 {%0, %1}, %2;" : "=f"(lo), "=f"(hi) : "l"(s))

// ---------------------------------------------------------------------------
// Winograd F(4x4,3x3) weight transform: U = G g G^T, stored [k=36][ci][co]
// ---------------------------------------------------------------------------
__global__ void k_wino_w(const float* __restrict__ w1){
  int i = blockIdx.x*256 + threadIdx.x;
  if (i >= CIN*CIN) return;
  int co = i & 255, ci = i >> 8;
  float g[3][3];
  #pragma unroll
  for (int m=0;m<3;m++)
    #pragma unroll
    for (int j=0;j<3;j++)
      g[m][j] = w1[((size_t)(co*CIN+ci)*3+m)*3+j];
  float T1[6][3];
  #pragma unroll
  for (int j=0;j<3;j++){
    float g0=g[0][j], g1=g[1][j], g2=g[2][j];
    T1[0][j] = 0.25f*g0;
    T1[1][j] = (-g0-g1-g2)*(1.f/6.f);
    T1[2][j] = (-g0+g1-g2)*(1.f/6.f);
    T1[3][j] = g0*(1.f/24.f)+g1*(1.f/12.f)+g2*(1.f/6.f);
    T1[4][j] = g0*(1.f/24.f)-g1*(1.f/12.f)+g2*(1.f/6.f);
    T1[5][j] = g2;
  }
  #pragma unroll
  for (int r=0;r<6;r++){
    float t0=T1[r][0], t1=T1[r][1], t2=T1[r][2];
    float u[6];
    u[0] = 0.25f*t0;
    u[1] = (-t0-t1-t2)*(1.f/6.f);
    u[2] = (-t0+t1-t2)*(1.f/6.f);
    u[3] = t0*(1.f/24.f)+t1*(1.f/12.f)+t2*(1.f/6.f);
    u[4] = t0*(1.f/24.f)-t1*(1.f/12.f)+t2*(1.f/6.f);
    u[5] = t2;
    #pragma unroll
    for (int c=0;c<6;c++)
      g_U[((size_t)(r*6+c)*CIN + ci)*CIN + co] = u[c];
  }
}

// ---------------------------------------------------------------------------
// Input transform: V = B^T d B per (tile, ci). Stored [k][ci][t].
// ---------------------------------------------------------------------------
__global__ void k_wino_in(const float* __restrict__ x){
  int t = blockIdx.x*256 + threadIdx.x;
  int ci = blockIdx.y;
  if (t >= NTILES) return;
  int b = t / TPB, rr = t - b*TPB;
  int ty = rr / 38, tx = rr - ty*38;
  int y0 = ty*4 - 1, xg0 = tx*4 - 1;
  const float* xp = x + ((size_t)b*CIN + ci)*HW;
  float d[6][6];
  #pragma unroll
  for (int m=0;m<6;m++){
    int gy = y0 + m;
    bool ry = ((unsigned)gy < HH);
    #pragma unroll
    for (int j=0;j<6;j++){
      int gx = xg0 + j;
      d[m][j] = (ry && (unsigned)gx < WW) ? xp[gy*WW + gx] : 0.f;
    }
  }
  float tmp[6][6];
  #pragma unroll
  for (int j=0;j<6;j++){
    float d0=d[0][j],d1=d[1][j],d2=d[2][j],d3=d[3][j],d4=d[4][j],d5=d[5][j];
    tmp[0][j] = 4.f*d0 - 5.f*d2 + d4;
    tmp[1][j] = -4.f*d1 - 4.f*d2 + d3 + d4;
    tmp[2][j] =  4.f*d1 - 4.f*d2 - d3 + d4;
    tmp[3][j] = -2.f*d1 - d2 + 2.f*d3 + d4;
    tmp[4][j] =  2.f*d1 - d2 - 2.f*d3 + d4;
    tmp[5][j] =  4.f*d1 - 5.f*d3 + d5;
  }
  #pragma unroll
  for (int i=0;i<6;i++){
    float r0=tmp[i][0],r1=tmp[i][1],r2=tmp[i][2],r3=tmp[i][3],r4=tmp[i][4],r5=tmp[i][5];
    float v[6];
    v[0] = 4.f*r0 - 5.f*r2 + r4;
    v[1] = -4.f*r1 - 4.f*r2 + r3 + r4;
    v[2] =  4.f*r1 - 4.f*r2 - r3 + r4;
    v[3] = -2.f*r1 - r2 + 2.f*r3 + r4;
    v[4] =  2.f*r1 - r2 - 2.f*r3 + r4;
    v[5] =  4.f*r1 - 5.f*r3 + r5;
    #pragma unroll
    for (int c=0;c<6;c++)
      g_V[((size_t)(i*6+c)*CIN + ci)*TPAD + t] = v[c];
  }
}

// ---------------------------------------------------------------------------
// GEMM v3 (unchanged from R10/R11 win): 128co x 128t, ci chunks of 16.
// ---------------------------------------------------------------------------
__global__ __launch_bounds__(256,2) void k_gemm(){
  __shared__ __align__(16) ull s_v[2][16][128];   // (v,v) pairs, 32KB
  __shared__ __align__(16) ull s_w[2][16][64];    // (w0,w1) pairs, 16KB
  int tid = threadIdx.x;
  int t0  = blockIdx.x*128;
  int co0 = blockIdx.y*128;
  int kk  = blockIdx.z;
  int og = tid & 15;       // co group: 8 co (4 pairs)
  int tg = tid >> 4;       // t group: 8 t
  const float* Vk = g_V + (size_t)kk*CIN*TPAD;
  const float* Uk = g_U + (size_t)kk*CIN*CIN;

  ull acc[4][8];
  #pragma unroll
  for (int p=0;p<4;p++)
    #pragma unroll
    for (int j=0;j<8;j++) PACK2(acc[p][j], 0.f, 0.f);

  int sci  = tid >> 5;
  int scol = tid & 31;

  float4 rv0 = *(const float4*)&Vk[(size_t)sci*TPAD + t0 + scol*4];
  float4 rv1 = *(const float4*)&Vk[(size_t)(sci+8)*TPAD + t0 + scol*4];
  float4 rw0 = *(const float4*)&Uk[(size_t)sci*CIN + co0 + scol*4];
  float4 rw1 = *(const float4*)&Uk[(size_t)(sci+8)*CIN + co0 + scol*4];
  {
    ull d0,d1,d2,d3;
    PACK2(d0,rv0.x,rv0.x); PACK2(d1,rv0.y,rv0.y);
    PACK2(d2,rv0.z,rv0.z); PACK2(d3,rv0.w,rv0.w);
    ull* dst = &s_v[0][sci][scol*4];
    dst[0]=d0; dst[1]=d1; dst[2]=d2; dst[3]=d3;
    PACK2(d0,rv1.x,rv1.x); PACK2(d1,rv1.y,rv1.y);
    PACK2(d2,rv1.z,rv1.z); PACK2(d3,rv1.w,rv1.w);
    dst = &s_v[0][sci+8][scol*4];
    dst[0]=d0; dst[1]=d1; dst[2]=d2; dst[3]=d3;
    ull w0,w1;
    PACK2(w0,rw0.x,rw0.y); PACK2(w1,rw0.z,rw0.w);
    s_w[0][sci][scol*2]   = w0;
    s_w[0][sci][scol*2+1] = w1;
    PACK2(w0,rw1.x,rw1.y); PACK2(w1,rw1.z,rw1.w);
    s_w[0][sci+8][scol*2]   = w0;
    s_w[0][sci+8][scol*2+1] = w1;
  }
  __syncthreads();

  #pragma unroll 1
  for (int c=0; c<16; c++){
    int buf = c & 1;
    if (c+1 < 16){
      int cin = (c+1)*16;
      rv0 = *(const float4*)&Vk[(size_t)(cin+sci)*TPAD + t0 + scol*4];
      rv1 = *(const float4*)&Vk[(size_t)(cin+sci+8)*TPAD + t0 + scol*4];
      rw0 = *(const float4*)&Uk[(size_t)(cin+sci)*CIN + co0 + scol*4];
      rw1 = *(const float4*)&Uk[(size_t)(cin+sci+8)*CIN + co0 + scol*4];
    }

    #pragma unroll 8
    for (int ci=0; ci<16; ci++){
      ulonglong2 v01 = *(const ulonglong2*)&s_v[buf][ci][tg*8];
      ulonglong2 v23 = *(const ulonglong2*)&s_v[buf][ci][tg*8+2];
      ulonglong2 v45 = *(const ulonglong2*)&s_v[buf][ci][tg*8+4];
      ulonglong2 v67 = *(const ulonglong2*)&s_v[buf][ci][tg*8+6];
      ulonglong2 wa = *(const ulonglong2*)&s_w[buf][ci][og*4];
      ulonglong2 wb = *(const ulonglong2*)&s_w[buf][ci][og*4+2];
      ull v[8] = {v01.x, v01.y, v23.x, v23.y, v45.x, v45.y, v67.x, v67.y};
      #pragma unroll
      for (int j=0;j<8;j++){
        FMA2(acc[0][j], v[j], wa.x, acc[0][j]);
        FMA2(acc[1][j], v[j], wa.y, acc[1][j]);
        FMA2(acc[2][j], v[j], wb.x, acc[2][j]);
        FMA2(acc[3][j], v[j], wb.y, acc[3][j]);
      }
    }

    if (c+1 < 16){
      int nb = buf ^ 1;
      ull d0,d1,d2,d3;
      PACK2(d0,rv0.x,rv0.x); PACK2(d1,rv0.y,rv0.y);
      PACK2(d2,rv0.z,rv0.z); PACK2(d3,rv0.w,rv0.w);
      ull* dst = &s_v[nb][sci][scol*4];
      dst[0]=d0; dst[1]=d1; dst[2]=d2; dst[3]=d3;
      PACK2(d0,rv1.x,rv1.x); PACK2(d1,rv1.y,rv1.y);
      PACK2(d2,rv1.z,rv1.z); PACK2(d3,rv1.w,rv1.w);
      dst = &s_v[nb][sci+8][scol*4];
      dst[0]=d0; dst[1]=d1; dst[2]=d2; dst[3]=d3;
      ull w0,w1;
      PACK2(w0,rw0.x,rw0.y); PACK2(w1,rw0.z,rw0.w);
      s_w[nb][sci][scol*2]   = w0;
      s_w[nb][sci][scol*2+1] = w1;
      PACK2(w0,rw1.x,rw1.y); PACK2(w1,rw1.z,rw1.w);
      s_w[nb][sci+8][scol*2]   = w0;
      s_w[nb][sci+8][scol*2+1] = w1;
    }
    __syncthreads();
  }

  float* Mk = g_M + (size_t)kk*CIN*TPAD;
  #pragma unroll
  for (int p=0;p<4;p++){
    float lo[8], hi[8];
    #pragma unroll
    for (int j=0;j<8;j++) UNPACK2(lo[j], hi[j], acc[p][j]);
    int co = co0 + og*8 + 2*p;
    float* r0 = &Mk[(size_t)co*TPAD + t0 + tg*8];
    float* r1 = &Mk[(size_t)(co+1)*TPAD + t0 + tg*8];
    *(float4*)r0     = make_float4(lo[0],lo[1],lo[2],lo[3]);
    *(float4*)(r0+4) = make_float4(lo[4],lo[5],lo[6],lo[7]);
    *(float4*)r1     = make_float4(hi[0],hi[1],hi[2],hi[3]);
    *(float4*)(r1+4) = make_float4(hi[4],hi[5],hi[6],hi[7]);
  }
}

// ---------------------------------------------------------------------------
// FUSED v5 = R14 structure (no templates, single code path) + half-split
// weight staging: s_w2[2][16][21] holds each half's 21 pairs (half1's 21st
// pair is zero-padded). Conv loop is a uniform 21 iterations with direct
// [half][ci][j] indexing -> no per-ci pointer math, no per-FMA predication.
// Pad pair multiplies zero weight into zero-init acc (exact +0) and is
// never emitted. Epilogue identical to R14.
// ---------------------------------------------------------------------------
#define NJ0 21   /* half 0: pairs 0..20 -> co 0..41 */
#define NJ1 20   /* half 1: pairs 21..40 -> co 42..81(pad) */

__global__ __launch_bounds__(512,1) void k_fused_out(const float* __restrict__ b1,
                                                     const float* __restrict__ w2,
                                                     const float* __restrict__ b2,
                                                     float* __restrict__ logits){
  __shared__ float s_hid[16][512];   // 32KB (reused in epilogue)
  __shared__ ull   s_w2[2][16][21];  // per-half weight pairs, 5.25KB
  int tid = threadIdx.x;
  int t0 = blockIdx.x*32;
  int co16 = tid >> 5;     // transform role: local co (0..15)
  int tl   = tid & 31;     // transform role: local tile (0..31)
  int t    = t0 + tl;
  int pxl  = tid & 255;    // conv role: pixels pxl and pxl+256
  int half = tid >> 8;     // conv role: co-half
  int j0   = half ? NJ0 : 0;
  int nj   = half ? NJ1 : NJ0;

  ull accA[NJ0], accB[NJ0];
  #pragma unroll
  for (int j=0;j<NJ0;j++){
    int gp = j0 + j;                 // global pair index
    if (j < nj){
      float ba = b2[2*gp];
      float bb = (2*gp+1 < 81) ? b2[2*gp+1] : 0.f;
      PACK2(accA[j], ba, bb);
    } else PACK2(accA[j], 0.f, 0.f);
    accB[j] = accA[j];
  }

  #pragma unroll 1
  for (int ch=0; ch<16; ch++){
    __syncthreads();
    // stage w2 chunk split by half: 2 x 16ci x 21 pairs = 672 entries
    #pragma unroll 1
    for (int i=tid; i<672; i+=512){
      int j = i % 21; int q = i/21; int ci = q & 15; int h = q >> 4;
      int gp = h*NJ0 + j;
      int cia = ch*16 + ci;
      float wa = 0.f, wb = 0.f;
      if (gp < 41){
        wa = w2[(2*gp)*CIN + cia];
        wb = (2*gp+1 < 81) ? w2[(2*gp+1)*CIN + cia] : 0.f;
      }
      ull d; PACK2(d, wa, wb);
      s_w2[h][ci][j] = d;
    }
    // transform: co = ch*16 + co16, tile t
    {
      int co = ch*16 + co16;
      const float* Mp = g_M + (size_t)co*TPAD + t;
      float bv = b1[co];
      float tr0[6], tr1[6], tr2[6], tr3[6];
      #pragma unroll
      for (int j=0;j<6;j++){
        float m0 = Mp[(size_t)(0*6+j)*CIN*TPAD];
        float m1 = Mp[(size_t)(1*6+j)*CIN*TPAD];
        float m2 = Mp[(size_t)(2*6+j)*CIN*TPAD];
        float m3 = Mp[(size_t)(3*6+j)*CIN*TPAD];
        float m4 = Mp[(size_t)(4*6+j)*CIN*TPAD];
        float m5 = Mp[(size_t)(5*6+j)*CIN*TPAD];
        tr0[j] = m0+m1+m2+m3+m4;
        tr1[j] = m1-m2+2.f*m3-2.f*m4;
        tr2[j] = m1+m2+4.f*m3+4.f*m4;
        tr3[j] = m1-m2+8.f*m3-8.f*m4+m5;
      }
      float* hrow = &s_hid[co16][tl*16];
      #pragma unroll
      for (int r=0;r<4;r++){
        const float* tr = (r==0)?tr0:((r==1)?tr1:((r==2)?tr2:tr3));
        float r0=tr[0],r1=tr[1],r2=tr[2],r3=tr[3],r4=tr[4],r5=tr[5];
        float y0 = r0+r1+r2+r3+r4;
        float y1 = r1-r2+2.f*r3-2.f*r4;
        float y2 = r1+r2+4.f*r3+4.f*r4;
        float y3 = r1-r2+8.f*r3-8.f*r4+r5;
        hrow[r*4+0] = fmaxf(y0+bv, 0.f);
        hrow[r*4+1] = fmaxf(y1+bv, 0.f);
        hrow[r*4+2] = fmaxf(y2+bv, 0.f);
        hrow[r*4+3] = fmaxf(y3+bv, 0.f);
      }
    }
    __syncthreads();
    // conv: uniform 21 pairs, direct indexing into this half's weight table
    const ull (*wph)[21] = (const ull (*)[21])s_w2[half];
    #pragma unroll 2
    for (int ci=0; ci<16; ci++){
      float vA = s_hid[ci][pxl];
      float vB = s_hid[ci][pxl+256];
      ull vdA, vdB; PACK2(vdA, vA, vA); PACK2(vdB, vB, vB);
      const ull* wp = wph[ci];
      #pragma unroll
      for (int j=0;j<NJ0;j++){
        ull w = wp[j];
        FMA2(accA[j], vdA, w, accA[j]);
        FMA2(accB[j], vdB, w, accB[j]);
      }
    }
  }

  // ---- epilogue: per-(half,px) reduction through smem (R14 layout) ----
  __syncthreads();
  float* base = (float*)s_hid;
  float* redM = base;                 // [2][512]
  float* redB = base + 1024;          // [2][512]
  float* redS = base + 2048;          // [2][512]
  int*   redI = (int*)(base + 3072);  // [2][512]

  #pragma unroll
  for (int s2=0;s2<2;s2++){
    int q = pxl + s2*256;
    int tile = t0 + (q >> 4);
    bool valid = (tile < NTILES);
    int b = tile / TPB, rr = tile - b*TPB;
    int ty = rr / 38, tx = rr - ty*38;
    int pos = q & 15;
    int px = (ty*4 + (pos>>2))*WW + tx*4 + (pos&3);
    float* ob = logits + (size_t)b*NC*HW;
    ull* acc = s2 ? accB : accA;

    float M = -1e30f, best = -1e30f; int bi = 0;
    #pragma unroll
    for (int j=0;j<NJ0;j++){
      if (j < nj){
        int jj = j0 + j;
        float a, c; UNPACK2(a, c, acc[j]);
        if (valid) ob[(size_t)(2*jj)*HW + px] = a;
        if (2*jj < 80 && a > best){ best = a; bi = 2*jj; }
        M = fmaxf(M, a);
        if (2*jj+1 < 81){
          if (valid) ob[(size_t)(2*jj+1)*HW + px] = c;
          if (2*jj+1 < 80 && c > best){ best = c; bi = 2*jj+1; }
          M = fmaxf(M, c);
        }
      }
    }
    redM[half*512 + q] = M;
    redB[half*512 + q] = best;
    redI[half*512 + q] = bi;
  }
  __syncthreads();
  #pragma unroll
  for (int s2=0;s2<2;s2++){
    int q = pxl + s2*256;
    float Mg = fmaxf(redM[q], redM[512 + q]);
    ull* acc = s2 ? accB : accA;
    float s = 0.f;
    #pragma unroll
    for (int j=0;j<NJ0;j++){
      if (j < nj){
        int jj = j0 + j;
        float a, c; UNPACK2(a, c, acc[j]);
        s += expf(a - Mg);
        if (2*jj+1 < 81) s += expf(c - Mg);
      }
    }
    redS[half*512 + q] = s;
  }
  __syncthreads();
  if (half==0){
    #pragma unroll
    for (int s2=0;s2<2;s2++){
      int q = pxl + s2*256;
      int tile = t0 + (q >> 4);
      if (tile >= NTILES) continue;
      int b = tile / TPB, rr = tile - b*TPB;
      int ty = rr / 38, tx = rr - ty*38;
      int pos = q & 15;
      int px = (ty*4 + (pos>>2))*WW + tx*4 + (pos&3);
      float Mg = fmaxf(redM[q], redM[512 + q]);
      float stot = redS[q] + redS[512 + q];
      float b0 = redB[q], b1v = redB[512 + q];
      int   i0 = redI[q], i1  = redI[512 + q];
      float bestg = b0; int big = i0;
      if (b1v > b0){ bestg = b1v; big = i1; }
      int gi = b*HW + px;
      g_pv[gi]  = expf(bestg - Mg) / stot;
      g_cls[gi] = big;
    }
  }
}

// ---------------------------------------------------------------------------
// score = p + 1 if local max (same-class strict neighbors) — unchanged.
// ---------------------------------------------------------------------------
__global__ void k_score(){
  int i = blockIdx.x*256 + threadIdx.x;
  if (i >= BATCH*HW) return;
  int b = i / HW, px = i - b*HW;
  int y = px / WW, xx = px - y*WW;
  float p = g_pv[i]; int cls = g_cls[i];
  bool flag = (p >= 1e-6f);
  if (flag){
    #pragma unroll
    for (int dy=-1; dy<=1; dy++){
      #pragma unroll
      for (int dx=-1; dx<=1; dx++){
        if (dy==0 && dx==0) continue;
        int ny = y+dy, nx = xx+dx;
        if ((unsigned)ny < HH && (unsigned)nx < WW){
          int j = b*HW + ny*WW + nx;
          if (g_cls[j]==cls && g_pv[j] > p) flag = false;
        }
      }
    }
  }
  float score = p + (flag ? 1.f : 0.f);
  g_keys[i] = (((ull)__float_as_uint(score))<<32)
              | (ull)(0xFFFFFFFFu - (unsigned)px);
}

// ---------------------------------------------------------------------------
// Top-100 v2 (unchanged from R11 win): stripe cache + shfl argmax.
// ---------------------------------------------------------------------------
__global__ void k_topk(){
  __shared__ ull s_val[256];
  __shared__ ull s_wv[8];
  __shared__ int s_wi[8];
  __shared__ int s_twin;
  int b = blockIdx.x, tid = threadIdx.x;
  int lane = tid & 31, wid = tid >> 5;
  ull* kb = g_keys + (size_t)b*HW;

  {
    ull m = 0ull;
    for (int i=tid; i<HW; i+=256){
      ull k = kb[i];
      if (k > m) m = k;
    }
    s_val[tid] = m;
  }
  __syncthreads();

  for (int it=0; it<NKEEP; it++){
    ull v = s_val[tid]; int idx = tid;
    #pragma unroll
    for (int off=16; off; off>>=1){
      ull ov  = __shfl_down_sync(0xFFFFFFFFu, v, off);
      int oi  = __shfl_down_sync(0xFFFFFFFFu, idx, off);
      if (ov > v){ v = ov; idx = oi; }
    }
    if (lane==0){ s_wv[wid] = v; s_wi[wid] = idx; }
    __syncthreads();
    if (tid==0){
      ull bv = s_wv[0]; int bidx = s_wi[0];
      #pragma unroll
      for (int w=1;w<8;w++)
        if (s_wv[w] > bv){ bv = s_wv[w]; bidx = s_wi[w]; }
      int wpx = (int)(0xFFFFFFFFu - (unsigned)(bv & 0xFFFFFFFFull));
      g_topk[b*NKEEP+it] = wpx;
      kb[wpx] = 0ull;
      s_twin = bidx;
    }
    __syncthreads();
    int twin = s_twin;
    if (wid==0){
      ull m = 0ull;
      int i0 = twin + lane*256, i1 = twin + (lane+32)*256;
      if (i0 < HW){ ull k = kb[i0]; if (k > m) m = k; }
      if (i1 < HW){ ull k = kb[i1]; if (k > m) m = k; }
      #pragma unroll
      for (int off=16; off; off>>=1){
        ull ov = __shfl_down_sync(0xFFFFFFFFu, m, off);
        if (ov > m) m = ov;
      }
      if (lane==0) s_val[twin] = m;
    }
    __syncthreads();
  }
}

// ---------------------------------------------------------------------------
// Gather x and pos at top-k indices. out layout: [proposals | pos | logits]
// ---------------------------------------------------------------------------
__global__ void k_gather(const float* __restrict__ x, const float* __restrict__ pos,
                         float* __restrict__ out){
  int i = blockIdx.x*256 + threadIdx.x;
  if (i >= NOUT1) return;
  int k = i % NKEEP; int t = i / NKEEP; int c = t % CIN; int b = t / CIN;
  int px = g_topk[b*NKEEP + k];
  out[i]         = x[((size_t)b*CIN + c)*HW + px];
  out[NOUT1 + i] = pos[(size_t)c*HW + px];
}

// ---------------------------------------------------------------------------
extern "C" void kernel_launch(void* const* d_in, const int* in_sizes, int n_in,
                              void* d_out, int out_size){
  (void)in_sizes; (void)n_in; (void)out_size;
  const float* x   = (const float*)d_in[0];
  const float* pos = (const float*)d_in[1];
  const float* w1  = (const float*)d_in[2];
  const float* b1  = (const float*)d_in[3];
  const float* w2  = (const float*)d_in[4];
  const float* b2  = (const float*)d_in[5];
  float* out = (float*)d_out;
  float* logits = out + 2*NOUT1;

  k_wino_w   <<<(CIN*CIN+255)/256, 256>>>(w1);
  k_wino_in  <<<dim3((NTILES+255)/256, CIN), 256>>>(x);
  k_gemm     <<<dim3(TPAD/128, CIN/128, 36), 256>>>();
  k_fused_out<<<TPAD/32, 512>>>(b1, w2, b2, logits);
  k_score    <<<(BATCH*HW+255)/256, 256>>>();
  k_topk     <<<BATCH, 256>>>();
  k_gather   <<<(NOUT1+255)/256, 256>>>(x, pos, out);
}

// round 17
// speedup vs baseline: 1.1021x; 1.0328x over previous
#include <cuda_runtime.h>
#include <math.h>

#define BATCH 8
#define CIN 256
#define HH 100
#define WW 152
#define HW 15200
#define NC 81
#define NKEEP 100
#define NOUT1 (BATCH*CIN*NKEEP)   /* 204800 */

#define NTILES 7600       /* 8 * 25 * 38 */
#define TPB    950        /* tiles per batch image */
#define TPAD   7680       /* padded tile count (60 * 128) */

typedef unsigned long long ull;

// ---------------------------------------------------------------------------
// Device scratch (allocation-free per harness rules)
// ---------------------------------------------------------------------------
__device__ int   g_cls[BATCH*HW];
__device__ float g_pv[BATCH*HW];
__device__ ull   g_keys[BATCH*HW];
__device__ int   g_topk[BATCH*NKEEP];
// Winograd buffers
__device__ float g_U[(size_t)36*CIN*CIN];         // weight transform [k][ci][co]
__device__ float g_V[(size_t)36*CIN*TPAD];        // input transform  [k][ci][t]
__device__ float g_M[(size_t)36*CIN*TPAD];        // GEMM output      [k][co][t]

// Packed f32x2 helpers (SASS FFMA2 — exact IEEE fp32)
#define FMA2(d,a,b,c) asm("fma.rn.f32x2 %0, %1, %2, %3;" : "=l"(d) : "l"(a), "l"(b), "l"(c))
#define PACK2(d,lo,hi) asm("mov.b64 %0, {%1, %2};" : "=l"(d) : "f"(lo), "f"(hi))
#define UNPACK2(lo,hi,s) asm("mov.b64 {%0, %1}, %2;" : "=f"(lo), "=f"(hi) : "l"(s))

// ---------------------------------------------------------------------------
// Winograd F(4x4,3x3) weight transform: U = G g G^T, stored [k=36][ci][co]
// ---------------------------------------------------------------------------
__global__ void k_wino_w(const float* __restrict__ w1){
  int i = blockIdx.x*256 + threadIdx.x;
  if (i >= CIN*CIN) return;
  int co = i & 255, ci = i >> 8;
  float g[3][3];
  #pragma unroll
  for (int m=0;m<3;m++)
    #pragma unroll
    for (int j=0;j<3;j++)
      g[m][j] = w1[((size_t)(co*CIN+ci)*3+m)*3+j];
  float T1[6][3];
  #pragma unroll
  for (int j=0;j<3;j++){
    float g0=g[0][j], g1=g[1][j], g2=g[2][j];
    T1[0][j] = 0.25f*g0;
    T1[1][j] = (-g0-g1-g2)*(1.f/6.f);
    T1[2][j] = (-g0+g1-g2)*(1.f/6.f);
    T1[3][j] = g0*(1.f/24.f)+g1*(1.f/12.f)+g2*(1.f/6.f);
    T1[4][j] = g0*(1.f/24.f)-g1*(1.f/12.f)+g2*(1.f/6.f);
    T1[5][j] = g2;
  }
  #pragma unroll
  for (int r=0;r<6;r++){
    float t0=T1[r][0], t1=T1[r][1], t2=T1[r][2];
    float u[6];
    u[0] = 0.25f*t0;
    u[1] = (-t0-t1-t2)*(1.f/6.f);
    u[2] = (-t0+t1-t2)*(1.f/6.f);
    u[3] = t0*(1.f/24.f)+t1*(1.f/12.f)+t2*(1.f/6.f);
    u[4] = t0*(1.f/24.f)-t1*(1.f/12.f)+t2*(1.f/6.f);
    u[5] = t2;
    #pragma unroll
    for (int c=0;c<6;c++)
      g_U[((size_t)(r*6+c)*CIN + ci)*CIN + co] = u[c];
  }
}

// ---------------------------------------------------------------------------
// Input transform: V = B^T d B per (tile, ci). Stored [k][ci][t].
// v2: 2 ci per thread (sequential) — amortizes tile-coordinate and address
// int-math over 2x work; memory pattern and math identical.
// ---------------------------------------------------------------------------
__global__ void k_wino_in(const float* __restrict__ x){
  int t = blockIdx.x*256 + threadIdx.x;
  int ci0 = blockIdx.y*2;
  if (t >= NTILES) return;
  int b = t / TPB, rr = t - b*TPB;
  int ty = rr / 38, tx = rr - ty*38;
  int y0 = ty*4 - 1, xg0 = tx*4 - 1;

  #pragma unroll 1
  for (int cc=0; cc<2; cc++){
    int ci = ci0 + cc;
    const float* xp = x + ((size_t)b*CIN + ci)*HW;
    float d[6][6];
    #pragma unroll
    for (int m=0;m<6;m++){
      int gy = y0 + m;
      bool ry = ((unsigned)gy < HH);
      #pragma unroll
      for (int j=0;j<6;j++){
        int gx = xg0 + j;
        d[m][j] = (ry && (unsigned)gx < WW) ? xp[gy*WW + gx] : 0.f;
      }
    }
    float tmp[6][6];
    #pragma unroll
    for (int j=0;j<6;j++){
      float d0=d[0][j],d1=d[1][j],d2=d[2][j],d3=d[3][j],d4=d[4][j],d5=d[5][j];
      tmp[0][j] = 4.f*d0 - 5.f*d2 + d4;
      tmp[1][j] = -4.f*d1 - 4.f*d2 + d3 + d4;
      tmp[2][j] =  4.f*d1 - 4.f*d2 - d3 + d4;
      tmp[3][j] = -2.f*d1 - d2 + 2.f*d3 + d4;
      tmp[4][j] =  2.f*d1 - d2 - 2.f*d3 + d4;
      tmp[5][j] =  4.f*d1 - 5.f*d3 + d5;
    }
    #pragma unroll
    for (int i=0;i<6;i++){
      float r0=tmp[i][0],r1=tmp[i][1],r2=tmp[i][2],r3=tmp[i][3],r4=tmp[i][4],r5=tmp[i][5];
      float v[6];
      v[0] = 4.f*r0 - 5.f*r2 + r4;
      v[1] = -4.f*r1 - 4.f*r2 + r3 + r4;
      v[2] =  4.f*r1 - 4.f*r2 - r3 + r4;
      v[3] = -2.f*r1 - r2 + 2.f*r3 + r4;
      v[4] =  2.f*r1 - r2 - 2.f*r3 + r4;
      v[5] =  4.f*r1 - 5.f*r3 + r5;
      #pragma unroll
      for (int c=0;c<6;c++)
        g_V[((size_t)(i*6+c)*CIN + ci)*TPAD + t] = v[c];
    }
  }
}

// ---------------------------------------------------------------------------
// GEMM v3 (unchanged from R10/R11 win): 128co x 128t, ci chunks of 16.
// ---------------------------------------------------------------------------
__global__ __launch_bounds__(256,2) void k_gemm(){
  __shared__ __align__(16) ull s_v[2][16][128];   // (v,v) pairs, 32KB
  __shared__ __align__(16) ull s_w[2][16][64];    // (w0,w1) pairs, 16KB
  int tid = threadIdx.x;
  int t0  = blockIdx.x*128;
  int co0 = blockIdx.y*128;
  int kk  = blockIdx.z;
  int og = tid & 15;       // co group: 8 co (4 pairs)
  int tg = tid >> 4;       // t group: 8 t
  const float* Vk = g_V + (size_t)kk*CIN*TPAD;
  const float* Uk = g_U + (size_t)kk*CIN*CIN;

  ull acc[4][8];
  #pragma unroll
  for (int p=0;p<4;p++)
    #pragma unroll
    for (int j=0;j<8;j++) PACK2(acc[p][j], 0.f, 0.f);

  int sci  = tid >> 5;
  int scol = tid & 31;

  float4 rv0 = *(const float4*)&Vk[(size_t)sci*TPAD + t0 + scol*4];
  float4 rv1 = *(const float4*)&Vk[(size_t)(sci+8)*TPAD + t0 + scol*4];
  float4 rw0 = *(const float4*)&Uk[(size_t)sci*CIN + co0 + scol*4];
  float4 rw1 = *(const float4*)&Uk[(size_t)(sci+8)*CIN + co0 + scol*4];
  {
    ull d0,d1,d2,d3;
    PACK2(d0,rv0.x,rv0.x); PACK2(d1,rv0.y,rv0.y);
    PACK2(d2,rv0.z,rv0.z); PACK2(d3,rv0.w,rv0.w);
    ull* dst = &s_v[0][sci][scol*4];
    dst[0]=d0; dst[1]=d1; dst[2]=d2; dst[3]=d3;
    PACK2(d0,rv1.x,rv1.x); PACK2(d1,rv1.y,rv1.y);
    PACK2(d2,rv1.z,rv1.z); PACK2(d3,rv1.w,rv1.w);
    dst = &s_v[0][sci+8][scol*4];
    dst[0]=d0; dst[1]=d1; dst[2]=d2; dst[3]=d3;
    ull w0,w1;
    PACK2(w0,rw0.x,rw0.y); PACK2(w1,rw0.z,rw0.w);
    s_w[0][sci][scol*2]   = w0;
    s_w[0][sci][scol*2+1] = w1;
    PACK2(w0,rw1.x,rw1.y); PACK2(w1,rw1.z,rw1.w);
    s_w[0][sci+8][scol*2]   = w0;
    s_w[0][sci+8][scol*2+1] = w1;
  }
  __syncthreads();

  #pragma unroll 1
  for (int c=0; c<16; c++){
    int buf = c & 1;
    if (c+1 < 16){
      int cin = (c+1)*16;
      rv0 = *(const float4*)&Vk[(size_t)(cin+sci)*TPAD + t0 + scol*4];
      rv1 = *(const float4*)&Vk[(size_t)(cin+sci+8)*TPAD + t0 + scol*4];
      rw0 = *(const float4*)&Uk[(size_t)(cin+sci)*CIN + co0 + scol*4];
      rw1 = *(const float4*)&Uk[(size_t)(cin+sci+8)*CIN + co0 + scol*4];
    }

    #pragma unroll 8
    for (int ci=0; ci<16; ci++){
      ulonglong2 v01 = *(const ulonglong2*)&s_v[buf][ci][tg*8];
      ulonglong2 v23 = *(const ulonglong2*)&s_v[buf][ci][tg*8+2];
      ulonglong2 v45 = *(const ulonglong2*)&s_v[buf][ci][tg*8+4];
      ulonglong2 v67 = *(const ulonglong2*)&s_v[buf][ci][tg*8+6];
      ulonglong2 wa = *(const ulonglong2*)&s_w[buf][ci][og*4];
      ulonglong2 wb = *(const ulonglong2*)&s_w[buf][ci][og*4+2];
      ull v[8] = {v01.x, v01.y, v23.x, v23.y, v45.x, v45.y, v67.x, v67.y};
      #pragma unroll
      for (int j=0;j<8;j++){
        FMA2(acc[0][j], v[j], wa.x, acc[0][j]);
        FMA2(acc[1][j], v[j], wa.y, acc[1][j]);
        FMA2(acc[2][j], v[j], wb.x, acc[2][j]);
        FMA2(acc[3][j], v[j], wb.y, acc[3][j]);
      }
    }

    if (c+1 < 16){
      int nb = buf ^ 1;
      ull d0,d1,d2,d3;
      PACK2(d0,rv0.x,rv0.x); PACK2(d1,rv0.y,rv0.y);
      PACK2(d2,rv0.z,rv0.z); PACK2(d3,rv0.w,rv0.w);
      ull* dst = &s_v[nb][sci][scol*4];
      dst[0]=d0; dst[1]=d1; dst[2]=d2; dst[3]=d3;
      PACK2(d0,rv1.x,rv1.x); PACK2(d1,rv1.y,rv1.y);
      PACK2(d2,rv1.z,rv1.z); PACK2(d3,rv1.w,rv1.w);
      dst = &s_v[nb][sci+8][scol*4];
      dst[0]=d0; dst[1]=d1; dst[2]=d2; dst[3]=d3;
      ull w0,w1;
      PACK2(w0,rw0.x,rw0.y); PACK2(w1,rw0.z,rw0.w);
      s_w[nb][sci][scol*2]   = w0;
      s_w[nb][sci][scol*2+1] = w1;
      PACK2(w0,rw1.x,rw1.y); PACK2(w1,rw1.z,rw1.w);
      s_w[nb][sci+8][scol*2]   = w0;
      s_w[nb][sci+8][scol*2+1] = w1;
    }
    __syncthreads();
  }

  float* Mk = g_M + (size_t)kk*CIN*TPAD;
  #pragma unroll
  for (int p=0;p<4;p++){
    float lo[8], hi[8];
    #pragma unroll
    for (int j=0;j<8;j++) UNPACK2(lo[j], hi[j], acc[p][j]);
    int co = co0 + og*8 + 2*p;
    float* r0 = &Mk[(size_t)co*TPAD + t0 + tg*8];
    float* r1 = &Mk[(size_t)(co+1)*TPAD + t0 + tg*8];
    *(float4*)r0     = make_float4(lo[0],lo[1],lo[2],lo[3]);
    *(float4*)(r0+4) = make_float4(lo[4],lo[5],lo[6],lo[7]);
    *(float4*)r1     = make_float4(hi[0],hi[1],hi[2],hi[3]);
    *(float4*)(r1+4) = make_float4(hi[4],hi[5],hi[6],hi[7]);
  }
}

// ---------------------------------------------------------------------------
// FUSED v3 (EXACT R14 source — measured 253us; do not restructure).
// Block = 32 tiles (512 px), 512 threads = (2 co-halves) x (256 lanes),
// each thread owns TWO pixels (pxl, pxl+256).
// ---------------------------------------------------------------------------
#define NJ0 21   /* half 0: pairs j=0..20  -> co 0..41  */
#define NJ1 20   /* half 1: pairs j=21..40 -> co 42..81 (81 = pad) */

__global__ __launch_bounds__(512,1) void k_fused_out(const float* __restrict__ b1,
                                                     const float* __restrict__ w2,
                                                     const float* __restrict__ b2,
                                                     float* __restrict__ logits){
  __shared__ float s_hid[16][512];   // [ci16][block px], 32KB (reused in epilogue)
  __shared__ ull   s_w2[16][41];     // (w[2j],w[2j+1]) per ci, 5.25KB
  int tid = threadIdx.x;
  int t0 = blockIdx.x*32;
  int co16 = tid >> 5;     // transform role: local co (0..15)
  int tl   = tid & 31;     // transform role: local tile (0..31)
  int t    = t0 + tl;
  int pxl  = tid & 255;    // conv role: pixels pxl and pxl+256
  int half = tid >> 8;     // conv role: co-half
  int j0   = half ? NJ0 : 0;
  int nj   = half ? NJ1 : NJ0;

  ull accA[NJ0], accB[NJ0];
  #pragma unroll
  for (int j=0;j<NJ0;j++){
    if (j < nj){
      int jj = j0 + j;
      float ba = b2[2*jj];
      float bb = (2*jj+1 < 81) ? b2[2*jj+1] : 0.f;
      PACK2(accA[j], ba, bb);
      accB[j] = accA[j];
    } else { PACK2(accA[j], 0.f, 0.f); accB[j] = accA[j]; }
  }

  #pragma unroll 1
  for (int ch=0; ch<16; ch++){
    __syncthreads();
    // stage w2 chunk (16 ci x 41 pairs)
    #pragma unroll 1
    for (int i=tid; i<16*41; i+=512){
      int j = i % 41; int ci = i/41;
      int cia = ch*16 + ci;
      float wa = w2[(2*j)*CIN + cia];
      float wb = (2*j+1 < 81) ? w2[(2*j+1)*CIN + cia] : 0.f;
      ull d; PACK2(d, wa, wb);
      s_w2[ci][j] = d;
    }
    // transform: co = ch*16 + co16, tile t
    {
      int co = ch*16 + co16;
      const float* Mp = g_M + (size_t)co*TPAD + t;
      float bv = b1[co];
      float tr0[6], tr1[6], tr2[6], tr3[6];
      #pragma unroll
      for (int j=0;j<6;j++){
        float m0 = Mp[(size_t)(0*6+j)*CIN*TPAD];
        float m1 = Mp[(size_t)(1*6+j)*CIN*TPAD];
        float m2 = Mp[(size_t)(2*6+j)*CIN*TPAD];
        float m3 = Mp[(size_t)(3*6+j)*CIN*TPAD];
        float m4 = Mp[(size_t)(4*6+j)*CIN*TPAD];
        float m5 = Mp[(size_t)(5*6+j)*CIN*TPAD];
        tr0[j] = m0+m1+m2+m3+m4;
        tr1[j] = m1-m2+2.f*m3-2.f*m4;
        tr2[j] = m1+m2+4.f*m3+4.f*m4;
        tr3[j] = m1-m2+8.f*m3-8.f*m4+m5;
      }
      float* hrow = &s_hid[co16][tl*16];
      #pragma unroll
      for (int r=0;r<4;r++){
        const float* tr = (r==0)?tr0:((r==1)?tr1:((r==2)?tr2:tr3));
        float r0=tr[0],r1=tr[1],r2=tr[2],r3=tr[3],r4=tr[4],r5=tr[5];
        float y0 = r0+r1+r2+r3+r4;
        float y1 = r1-r2+2.f*r3-2.f*r4;
        float y2 = r1+r2+4.f*r3+4.f*r4;
        float y3 = r1-r2+8.f*r3-8.f*r4+r5;
        hrow[r*4+0] = fmaxf(y0+bv, 0.f);
        hrow[r*4+1] = fmaxf(y1+bv, 0.f);
        hrow[r*4+2] = fmaxf(y2+bv, 0.f);
        hrow[r*4+3] = fmaxf(y3+bv, 0.f);
      }
    }
    __syncthreads();
    // conv: thread owns (pxl & pxl+256, co-half). Weights loaded once per ci.
    #pragma unroll 2
    for (int ci=0; ci<16; ci++){
      float vA = s_hid[ci][pxl];
      float vB = s_hid[ci][pxl+256];
      ull vdA, vdB; PACK2(vdA, vA, vA); PACK2(vdB, vB, vB);
      const ull* wp = s_w2[ci] + j0;
      #pragma unroll
      for (int j=0;j<NJ0;j++){
        if (j < nj){
          ull w = wp[j];
          FMA2(accA[j], vdA, w, accA[j]);
          FMA2(accB[j], vdB, w, accB[j]);
        }
      }
    }
  }

  // ---- epilogue: per-(half,px) reduction through smem ----
  __syncthreads();
  float* base = (float*)s_hid;
  float* redM = base;                 // [2][512]
  float* redB = base + 1024;
  float* redS = base + 2048;
  int*   redI = (int*)(base + 3072);

  #pragma unroll
  for (int s2=0;s2<2;s2++){
    int q = pxl + s2*256;
    int tile = t0 + (q >> 4);
    bool valid = (tile < NTILES);
    int b = tile / TPB, rr = tile - b*TPB;
    int ty = rr / 38, tx = rr - ty*38;
    int pos = q & 15;
    int px = (ty*4 + (pos>>2))*WW + tx*4 + (pos&3);
    float* ob = logits + (size_t)b*NC*HW;
    ull* acc = s2 ? accB : accA;

    float M = -1e30f, best = -1e30f; int bi = 0;
    #pragma unroll
    for (int j=0;j<NJ0;j++){
      if (j < nj){
        int jj = j0 + j;
        float a, c; UNPACK2(a, c, acc[j]);
        if (valid) ob[(size_t)(2*jj)*HW + px] = a;
        if (2*jj < 80 && a > best){ best = a; bi = 2*jj; }
        M = fmaxf(M, a);
        if (2*jj+1 < 81){
          if (valid) ob[(size_t)(2*jj+1)*HW + px] = c;
          if (2*jj+1 < 80 && c > best){ best = c; bi = 2*jj+1; }
          M = fmaxf(M, c);
        }
      }
    }
    redM[half*512 + q] = M;
    redB[half*512 + q] = best;
    redI[half*512 + q] = bi;
  }
  __syncthreads();
  #pragma unroll
  for (int s2=0;s2<2;s2++){
    int q = pxl + s2*256;
    float Mg = fmaxf(redM[q], redM[512 + q]);
    ull* acc = s2 ? accB : accA;
    float s = 0.f;
    #pragma unroll
    for (int j=0;j<NJ0;j++){
      if (j < nj){
        int jj = j0 + j;
        float a, c; UNPACK2(a, c, acc[j]);
        s += expf(a - Mg);
        if (2*jj+1 < 81) s += expf(c - Mg);
      }
    }
    redS[half*512 + q] = s;
  }
  __syncthreads();
  if (half==0){
    #pragma unroll
    for (int s2=0;s2<2;s2++){
      int q = pxl + s2*256;
      int tile = t0 + (q >> 4);
      if (tile >= NTILES) continue;
      int b = tile / TPB, rr = tile - b*TPB;
      int ty = rr / 38, tx = rr - ty*38;
      int pos = q & 15;
      int px = (ty*4 + (pos>>2))*WW + tx*4 + (pos&3);
      float Mg = fmaxf(redM[q], redM[512 + q]);
      float stot = redS[q] + redS[512 + q];
      float b0 = redB[q], b1v = redB[512 + q];
      int   i0 = redI[q], i1  = redI[512 + q];
      float bestg = b0; int big = i0;
      if (b1v > b0){ bestg = b1v; big = i1; }
      int gi = b*HW + px;
      g_pv[gi]  = expf(bestg - Mg) / stot;
      g_cls[gi] = big;
    }
  }
}

// ---------------------------------------------------------------------------
// score = p + 1 if local max (same-class strict neighbors) — unchanged.
// ---------------------------------------------------------------------------
__global__ void k_score(){
  int i = blockIdx.x*256 + threadIdx.x;
  if (i >= BATCH*HW) return;
  int b = i / HW, px = i - b*HW;
  int y = px / WW, xx = px - y*WW;
  float p = g_pv[i]; int cls = g_cls[i];
  bool flag = (p >= 1e-6f);
  if (flag){
    #pragma unroll
    for (int dy=-1; dy<=1; dy++){
      #pragma unroll
      for (int dx=-1; dx<=1; dx++){
        if (dy==0 && dx==0) continue;
        int ny = y+dy, nx = xx+dx;
        if ((unsigned)ny < HH && (unsigned)nx < WW){
          int j = b*HW + ny*WW + nx;
          if (g_cls[j]==cls && g_pv[j] > p) flag = false;
        }
      }
    }
  }
  float score = p + (flag ? 1.f : 0.f);
  g_keys[i] = (((ull)__float_as_uint(score))<<32)
              | (ull)(0xFFFFFFFFu - (unsigned)px);
}

// ---------------------------------------------------------------------------
// Top-100 v2 (unchanged from R11 win): stripe cache + shfl argmax.
// ---------------------------------------------------------------------------
__global__ void k_topk(){
  __shared__ ull s_val[256];
  __shared__ ull s_wv[8];
  __shared__ int s_wi[8];
  __shared__ int s_twin;
  int b = blockIdx.x, tid = threadIdx.x;
  int lane = tid & 31, wid = tid >> 5;
  ull* kb = g_keys + (size_t)b*HW;

  {
    ull m = 0ull;
    for (int i=tid; i<HW; i+=256){
      ull k = kb[i];
      if (k > m) m = k;
    }
    s_val[tid] = m;
  }
  __syncthreads();

  for (int it=0; it<NKEEP; it++){
    ull v = s_val[tid]; int idx = tid;
    #pragma unroll
    for (int off=16; off; off>>=1){
      ull ov  = __shfl_down_sync(0xFFFFFFFFu, v, off);
      int oi  = __shfl_down_sync(0xFFFFFFFFu, idx, off);
      if (ov > v){ v = ov; idx = oi; }
    }
    if (lane==0){ s_wv[wid] = v; s_wi[wid] = idx; }
    __syncthreads();
    if (tid==0){
      ull bv = s_wv[0]; int bidx = s_wi[0];
      #pragma unroll
      for (int w=1;w<8;w++)
        if (s_wv[w] > bv){ bv = s_wv[w]; bidx = s_wi[w]; }
      int wpx = (int)(0xFFFFFFFFu - (unsigned)(bv & 0xFFFFFFFFull));
      g_topk[b*NKEEP+it] = wpx;
      kb[wpx] = 0ull;
      s_twin = bidx;
    }
    __syncthreads();
    int twin = s_twin;
    if (wid==0){
      ull m = 0ull;
      int i0 = twin + lane*256, i1 = twin + (lane+32)*256;
      if (i0 < HW){ ull k = kb[i0]; if (k > m) m = k; }
      if (i1 < HW){ ull k = kb[i1]; if (k > m) m = k; }
      #pragma unroll
      for (int off=16; off; off>>=1){
        ull ov = __shfl_down_sync(0xFFFFFFFFu, m, off);
        if (ov > m) m = ov;
      }
      if (lane==0) s_val[twin] = m;
    }
    __syncthreads();
  }
}

// ---------------------------------------------------------------------------
// Gather x and pos at top-k indices. out layout: [proposals | pos | logits]
// ---------------------------------------------------------------------------
__global__ void k_gather(const float* __restrict__ x, const float* __restrict__ pos,
                         float* __restrict__ out){
  int i = blockIdx.x*256 + threadIdx.x;
  if (i >= NOUT1) return;
  int k = i % NKEEP; int t = i / NKEEP; int c = t % CIN; int b = t / CIN;
  int px = g_topk[b*NKEEP + k];
  out[i]         = x[((size_t)b*CIN + c)*HW + px];
  out[NOUT1 + i] = pos[(size_t)c*HW + px];
}

// ---------------------------------------------------------------------------
extern "C" void kernel_launch(void* const* d_in, const int* in_sizes, int n_in,
                              void* d_out, int out_size){
  (void)in_sizes; (void)n_in; (void)out_size;
  const float* x   = (const float*)d_in[0];
  const float* pos = (const float*)d_in[1];
  const float* w1  = (const float*)d_in[2];
  const float* b1  = (const float*)d_in[3];
  const float* w2  = (const float*)d_in[4];
  const float* b2  = (const float*)d_in[5];
  float* out = (float*)d_out;
  float* logits = out + 2*NOUT1;

  k_wino_w   <<<(CIN*CIN+255)/256, 256>>>(w1);
  k_wino_in  <<<dim3((NTILES+255)/256, CIN/2), 256>>>(x);
  k_gemm     <<<dim3(TPAD/128, CIN/128, 36), 256>>>();
  k_fused_out<<<TPAD/32, 512>>>(b1, w2, b2, logits);
  k_score    <<<(BATCH*HW+255)/256, 256>>>();
  k_topk     <<<BATCH, 256>>>();
  k_gather   <<<(NOUT1+255)/256, 256>>>(x, pos, out);
}